// round 8
// baseline (speedup 1.0000x reference)
#include <cuda_runtime.h>
#include <stdint.h>
#include <float.h>

// ChamferLoss2D: N=16, P=4096, D=2.
// cost_n = 0.5*(mean_i min_j C + mean_j min_i C), C = sqrt(clip(|x-y|^2, EPS))
// out = mean_n cost_n * (sum(set2_n) >= 0)
//
// Grid NN, exact, SMEM-resident (points 32KB + u16 cell table 12.8KB per
// block). Fast path scans the 3x3 cell box with an interleaved 3-cursor loop:
// all 6 row bounds prefetched, 3 LDS point-loads in flight per iteration,
// 3 independent min chains. Ring expansion with edge-aware lower bound
// (clamped sides => inf) handles the sparse tail; exact for ANY input.

#define N_BATCH 16
#define P 4096

#define G 80
#define CELLS (G * G)            // 6400
#define CS_PAD (CELLS + 2)

#define DOM_LO (-5.2f)
#define DOM_W  (10.4f)
#define CELL_W (DOM_W / (float)G)
#define INV_W  ((float)G / DOM_W)

#define EPS 1e-12f
#define OUT_WT (0.5f / (float)P / (float)N_BATCH)

__device__ float2   g_pts[2][N_BATCH][P];           // cell-sorted points
__device__ uint16_t g_cellstart[2][N_BATCH][CS_PAD];
__device__ float    g_mask[N_BATCH];

__device__ __forceinline__ int cell_coord(float v) {
    int c = (int)((v - DOM_LO) * INV_W);
    return min(max(c, 0), G - 1);
}

// ---- build: one block of 512 per (set, batch) -------------------------------
#define TPB_B 512
#define PPT_B (P / TPB_B)        // 8
#define CELLS_PADB 6656          // 512 * 13
#define CPT_B 13

__global__ void __launch_bounds__(TPB_B) build_kernel(
    const float* __restrict__ s1, const float* __restrict__ s2,
    float* __restrict__ out) {
    const int set = blockIdx.x >> 4;
    const int n   = blockIdx.x & 15;
    const float2* __restrict__ src =
        (const float2*)((set ? s2 : s1) + (size_t)n * P * 2);

    __shared__ uint32_t s_cnt[CELLS_PADB];
    __shared__ uint32_t s_wsum[TPB_B / 32];
    __shared__ float    s_red[TPB_B / 32];

    const int t = threadIdx.x;
    const int lane = t & 31, w = t >> 5;

#pragma unroll
    for (int k = 0; k < CPT_B; k++) s_cnt[k * TPB_B + t] = 0;
    __syncthreads();

    float2 pt[PPT_B];
    int    cid[PPT_B];
    float  msum = 0.0f;
#pragma unroll
    for (int k = 0; k < PPT_B; k++) {
        float2 p = src[k * TPB_B + t];
        pt[k] = p;
        cid[k] = cell_coord(p.y) * G + cell_coord(p.x);
        atomicAdd(&s_cnt[cid[k]], 1u);
        msum += p.x + p.y;
    }
    __syncthreads();

    uint32_t tot = 0;
#pragma unroll
    for (int c = 0; c < CPT_B; c++) tot += s_cnt[t * CPT_B + c];
    uint32_t inc = tot;
#pragma unroll
    for (int o = 1; o < 32; o <<= 1) {
        uint32_t v = __shfl_up_sync(0xffffffffu, inc, o);
        if (lane >= o) inc += v;
    }
    if (lane == 31) s_wsum[w] = inc;
    uint32_t excl = inc - tot;
    __syncthreads();
    uint32_t wbase = 0;
#pragma unroll
    for (int ww = 0; ww < TPB_B / 32; ww++) {
        uint32_t v = s_wsum[ww];
        if (ww < w) wbase += v;
    }
    uint32_t run = wbase + excl;
#pragma unroll
    for (int c = 0; c < CPT_B; c++) {
        uint32_t v = s_cnt[t * CPT_B + c];
        s_cnt[t * CPT_B + c] = run;
        run += v;
    }
    __syncthreads();

    uint16_t* __restrict__ gs = g_cellstart[set][n];
#pragma unroll
    for (int k = 0; k < CPT_B; k++) {
        int i = k * TPB_B + t;
        if (i < CS_PAD) gs[i] = (uint16_t)s_cnt[i];
    }
    __syncthreads();

    float2* __restrict__ gp = g_pts[set][n];
#pragma unroll
    for (int k = 0; k < PPT_B; k++) {
        uint32_t pos = atomicAdd(&s_cnt[cid[k]], 1u);
        gp[pos] = pt[k];
    }

#pragma unroll
    for (int o = 16; o > 0; o >>= 1) msum += __shfl_down_sync(0xffffffffu, msum, o);
    if (lane == 0) s_red[w] = msum;
    __syncthreads();
    if (t == 0) {
        float a = 0.0f;
#pragma unroll
        for (int ww = 0; ww < TPB_B / 32; ww++) a += s_red[ww];
        if (set == 1) g_mask[n] = (a >= 0.0f) ? 1.0f : 0.0f;
        if (set == 0 && n == 0) out[0] = 0.0f;
    }
}

// ---- query ------------------------------------------------------------------
#define TPB 256

__device__ __forceinline__ float sqd(float2 q, float2 p) {
    float dx = q.x - p.x;
    float dy = q.y - p.y;
    return fmaf(dx, dx, dy * dy);
}

__device__ __forceinline__ void scan_run(
    const float2* pts, int s, int e, float2 q, float& best) {
    for (int idx = s; idx < e; idx++)
        best = fminf(best, sqd(q, pts[idx]));
}

// Lower bound to unscanned region outside box radius r; clamped sides => inf.
__device__ __forceinline__ float box_lb(float qx, float qy, int cx, int cy, int r) {
    float l  = (cx - r <= 0)     ? FLT_MAX : qx - (DOM_LO + (float)(cx - r) * CELL_W);
    float rt = (cx + r >= G - 1) ? FLT_MAX : (DOM_LO + (float)(cx + r + 1) * CELL_W) - qx;
    float b  = (cy - r <= 0)     ? FLT_MAX : qy - (DOM_LO + (float)(cy - r) * CELL_W);
    float tp = (cy + r >= G - 1) ? FLT_MAX : (DOM_LO + (float)(cy + r + 1) * CELL_W) - qy;
    return fminf(fminf(l, rt), fminf(b, tp));
}

__global__ void __launch_bounds__(TPB) query_kernel(float* __restrict__ out) {
    // blockIdx: [dir(2)][n(16)][chunk(16)]
    const int chunk = blockIdx.x & 15;
    const int n     = (blockIdx.x >> 4) & 15;
    const int dir   = blockIdx.x >> 8;
    const int dst   = 1 - dir;
    const int t     = threadIdx.x;
    const int lane  = t & 31;

    __shared__ __align__(16) float2   s_pts[P];       // 32 KB
    __shared__ __align__(4)  uint16_t s_cs[CS_PAD];   // 12.8 KB
    __shared__ float s_red[TPB / 32];

    // Copy destination structure into smem (L2 hits, coalesced).
    {
        const float4* gp4 = (const float4*)g_pts[dst][n];
        float4* sp4 = (float4*)s_pts;
#pragma unroll
        for (int k = 0; k < (P / 2) / TPB; k++)
            sp4[k * TPB + t] = gp4[k * TPB + t];
        const uint32_t* gc = (const uint32_t*)g_cellstart[dst][n];
        uint32_t* sc = (uint32_t*)s_cs;
        for (int i = t; i < CS_PAD / 2; i += TPB)
            sc[i] = gc[i];
    }

    const float2 q = g_pts[dir][n][chunk * TPB + t];
    const int cx = cell_coord(q.x);
    const int cy = cell_coord(q.y);

    __syncthreads();

    // ---- fast path: 3x3 box, interleaved 3-cursor scan ----
    const int ilo = max(cx - 1, 0), iw = min(cx + 1, G - 1) + 1;
    const int j0 = max(cy - 1, 0);
    const int j2 = min(cy + 1, G - 1);

    // Prefetch all row bounds (6 independent LDS; clamp rows predicated).
    int s0 = s_cs[j0 * G + ilo], e0 = s_cs[j0 * G + iw];
    int s1 = s_cs[cy * G + ilo], e1 = s_cs[cy * G + iw];
    int s2 = s_cs[j2 * G + ilo], e2 = s_cs[j2 * G + iw];
    if (j0 == cy) e0 = s0;     // cy-1 clamped away -> empty
    if (j2 == cy) e2 = s2;     // cy+1 clamped away -> empty

    float b0 = FLT_MAX, b1 = FLT_MAX, b2 = FLT_MAX;
    {
        int i0 = s0, i1 = s1, i2 = s2;
        while ((i0 < e0) | (i1 < e1) | (i2 < e2)) {
            const bool a0 = i0 < e0, a1 = i1 < e1, a2 = i2 < e2;
            float2 p0 = s_pts[a0 ? i0 : 0];
            float2 p1 = s_pts[a1 ? i1 : 0];
            float2 p2 = s_pts[a2 ? i2 : 0];
            b0 = fminf(b0, a0 ? sqd(q, p0) : FLT_MAX);
            b1 = fminf(b1, a1 ? sqd(q, p1) : FLT_MAX);
            b2 = fminf(b2, a2 ? sqd(q, p2) : FLT_MAX);
            i0 += a0; i1 += a1; i2 += a2;
        }
    }
    float best = fminf(b0, fminf(b1, b2));

    // ---- ring expansion (rare tail; edge-aware lb kills outliers at r=1) ----
    int r = 1;
    while (true) {
        float lb = box_lb(q.x, q.y, cx, cy, r);
        if (best <= lb * lb) break;       // inf^2 covers clamped/full coverage
        r++;
        int rlo = max(cx - r, 0), rhi = min(cx + r, G - 1);
        int jt = cy - r, jb = cy + r;
        if (jt >= 0)
            scan_run(s_pts, s_cs[jt * G + rlo], s_cs[jt * G + rhi + 1], q, best);
        if (jb <= G - 1)
            scan_run(s_pts, s_cs[jb * G + rlo], s_cs[jb * G + rhi + 1], q, best);
        int jlo2 = max(cy - r + 1, 0), jhi2 = min(cy + r - 1, G - 1);
        for (int j = jlo2; j <= jhi2; j++) {
            if (cx - r >= 0) {
                int c = j * G + (cx - r);
                scan_run(s_pts, s_cs[c], s_cs[c + 1], q, best);
            }
            if (cx + r <= G - 1) {
                int c = j * G + (cx + r);
                scan_run(s_pts, s_cs[c], s_cs[c + 1], q, best);
            }
        }
    }

    float d = sqrtf(fmaxf(best, EPS));

    // Block reduce (all threads in block share (dir, n)).
#pragma unroll
    for (int o = 16; o > 0; o >>= 1) d += __shfl_down_sync(0xffffffffu, d, o);
    if (lane == 0) s_red[t >> 5] = d;
    __syncthreads();
    if (t == 0) {
        float a = 0.0f;
#pragma unroll
        for (int ww = 0; ww < TPB / 32; ww++) a += s_red[ww];
        atomicAdd(out, a * g_mask[n] * OUT_WT);
    }
}

extern "C" void kernel_launch(void* const* d_in, const int* in_sizes, int n_in,
                              void* d_out, int out_size) {
    const float* s1 = (const float*)d_in[0];  // point_set_1: [16,4096,2] f32
    const float* s2 = (const float*)d_in[1];  // point_set_2: [16,4096,2] f32
    float* out = (float*)d_out;

    build_kernel<<<2 * N_BATCH, TPB_B>>>(s1, s2, out);
    query_kernel<<<2 * N_BATCH * (P / TPB), TPB>>>(out);
}

// round 9
// speedup vs baseline: 1.0182x; 1.0182x over previous
#include <cuda_runtime.h>
#include <stdint.h>
#include <float.h>

// ChamferLoss2D: N=16, P=4096, D=2.
// cost_n = 0.5*(mean_i min_j C + mean_j min_i C), C = sqrt(clip(|x-y|^2, EPS))
// out = mean_n cost_n * (sum(set2_n) >= 0)
//
// Grid NN, exact, SMEM-resident (points 32KB + u16 cell table 12.8KB per
// block). Queries stay warp-contiguous (low intra-warp divergence) but warps
// are dealt to blocks round-robin across the cell-sorted order, so every
// block gets a uniform dense/sparse mix (kills the dense-center straggler
// blocks). Ring expansion with edge-aware lower bound (clamped sides => inf)
// handles the sparse tail; exact for ANY input.

#define N_BATCH 16
#define P 4096

#define G 80
#define CELLS (G * G)            // 6400
#define CS_PAD (CELLS + 2)

#define DOM_LO (-5.2f)
#define DOM_W  (10.4f)
#define CELL_W (DOM_W / (float)G)
#define INV_W  ((float)G / DOM_W)

#define EPS 1e-12f
#define OUT_WT (0.5f / (float)P / (float)N_BATCH)

__device__ float2   g_pts[2][N_BATCH][P];           // cell-sorted points
__device__ uint16_t g_cellstart[2][N_BATCH][CS_PAD];
__device__ float    g_mask[N_BATCH];

__device__ __forceinline__ int cell_coord(float v) {
    int c = (int)((v - DOM_LO) * INV_W);
    return min(max(c, 0), G - 1);
}

// ---- build: one block of 512 per (set, batch) -------------------------------
#define TPB_B 512
#define PPT_B (P / TPB_B)        // 8
#define CELLS_PADB 6656          // 512 * 13
#define CPT_B 13

__global__ void __launch_bounds__(TPB_B) build_kernel(
    const float* __restrict__ s1, const float* __restrict__ s2,
    float* __restrict__ out) {
    const int set = blockIdx.x >> 4;
    const int n   = blockIdx.x & 15;
    const float2* __restrict__ src =
        (const float2*)((set ? s2 : s1) + (size_t)n * P * 2);

    __shared__ uint32_t s_cnt[CELLS_PADB];
    __shared__ uint32_t s_wsum[TPB_B / 32];
    __shared__ float    s_red[TPB_B / 32];

    const int t = threadIdx.x;
    const int lane = t & 31, w = t >> 5;

#pragma unroll
    for (int k = 0; k < CPT_B; k++) s_cnt[k * TPB_B + t] = 0;
    __syncthreads();

    float2 pt[PPT_B];
    int    cid[PPT_B];
    float  msum = 0.0f;
#pragma unroll
    for (int k = 0; k < PPT_B; k++) {
        float2 p = src[k * TPB_B + t];
        pt[k] = p;
        cid[k] = cell_coord(p.y) * G + cell_coord(p.x);
        atomicAdd(&s_cnt[cid[k]], 1u);
        msum += p.x + p.y;
    }
    __syncthreads();

    uint32_t tot = 0;
#pragma unroll
    for (int c = 0; c < CPT_B; c++) tot += s_cnt[t * CPT_B + c];
    uint32_t inc = tot;
#pragma unroll
    for (int o = 1; o < 32; o <<= 1) {
        uint32_t v = __shfl_up_sync(0xffffffffu, inc, o);
        if (lane >= o) inc += v;
    }
    if (lane == 31) s_wsum[w] = inc;
    uint32_t excl = inc - tot;
    __syncthreads();
    uint32_t wbase = 0;
#pragma unroll
    for (int ww = 0; ww < TPB_B / 32; ww++) {
        uint32_t v = s_wsum[ww];
        if (ww < w) wbase += v;
    }
    uint32_t run = wbase + excl;
#pragma unroll
    for (int c = 0; c < CPT_B; c++) {
        uint32_t v = s_cnt[t * CPT_B + c];
        s_cnt[t * CPT_B + c] = run;
        run += v;
    }
    __syncthreads();

    uint16_t* __restrict__ gs = g_cellstart[set][n];
#pragma unroll
    for (int k = 0; k < CPT_B; k++) {
        int i = k * TPB_B + t;
        if (i < CS_PAD) gs[i] = (uint16_t)s_cnt[i];
    }
    __syncthreads();

    float2* __restrict__ gp = g_pts[set][n];
#pragma unroll
    for (int k = 0; k < PPT_B; k++) {
        uint32_t pos = atomicAdd(&s_cnt[cid[k]], 1u);
        gp[pos] = pt[k];
    }

#pragma unroll
    for (int o = 16; o > 0; o >>= 1) msum += __shfl_down_sync(0xffffffffu, msum, o);
    if (lane == 0) s_red[w] = msum;
    __syncthreads();
    if (t == 0) {
        float a = 0.0f;
#pragma unroll
        for (int ww = 0; ww < TPB_B / 32; ww++) a += s_red[ww];
        if (set == 1) g_mask[n] = (a >= 0.0f) ? 1.0f : 0.0f;
        if (set == 0 && n == 0) out[0] = 0.0f;
    }
}

// ---- query ------------------------------------------------------------------
#define TPB 256

__device__ __forceinline__ float sqd(float2 q, float2 p) {
    float dx = q.x - p.x;
    float dy = q.y - p.y;
    return fmaf(dx, dx, dy * dy);
}

__device__ __forceinline__ void scan_run(
    const float2* pts, int s, int e, float2 q, float& best) {
    for (int idx = s; idx < e; idx++)
        best = fminf(best, sqd(q, pts[idx]));
}

// Lower bound to unscanned region outside box radius r; clamped sides => inf.
__device__ __forceinline__ float box_lb(float qx, float qy, int cx, int cy, int r) {
    float l  = (cx - r <= 0)     ? FLT_MAX : qx - (DOM_LO + (float)(cx - r) * CELL_W);
    float rt = (cx + r >= G - 1) ? FLT_MAX : (DOM_LO + (float)(cx + r + 1) * CELL_W) - qx;
    float b  = (cy - r <= 0)     ? FLT_MAX : qy - (DOM_LO + (float)(cy - r) * CELL_W);
    float tp = (cy + r >= G - 1) ? FLT_MAX : (DOM_LO + (float)(cy + r + 1) * CELL_W) - qy;
    return fminf(fminf(l, rt), fminf(b, tp));
}

__global__ void __launch_bounds__(TPB) query_kernel(float* __restrict__ out) {
    // blockIdx: [dir(2)][n(16)][chunk(16)]
    const int chunk = blockIdx.x & 15;
    const int n     = (blockIdx.x >> 4) & 15;
    const int dir   = blockIdx.x >> 8;
    const int dst   = 1 - dir;
    const int t     = threadIdx.x;
    const int lane  = t & 31;
    const int w     = t >> 5;

    __shared__ __align__(16) float2   s_pts[P];       // 32 KB
    __shared__ __align__(4)  uint16_t s_cs[CS_PAD];   // 12.8 KB
    __shared__ float s_red[TPB / 32];

    // Copy destination structure into smem (L2 hits, coalesced).
    {
        const float4* gp4 = (const float4*)g_pts[dst][n];
        float4* sp4 = (float4*)s_pts;
#pragma unroll
        for (int k = 0; k < (P / 2) / TPB; k++)
            sp4[k * TPB + t] = gp4[k * TPB + t];
        const uint32_t* gc = (const uint32_t*)g_cellstart[dst][n];
        uint32_t* sc = (uint32_t*)s_cs;
        for (int i = t; i < CS_PAD / 2; i += TPB)
            sc[i] = gc[i];
    }

    // Warp-shuffled query assignment: warp (w) of chunk (chunk) owns the
    // contiguous sorted run [(w*16+chunk)*32, +32) -> every block gets a
    // uniform mix of dense and sparse regions.
    const int qidx = (w * 16 + chunk) * 32 + lane;
    const float2 q = g_pts[dir][n][qidx];
    const int cx = cell_coord(q.x);
    const int cy = cell_coord(q.y);

    __syncthreads();

    float best = FLT_MAX;

    // Fast path: 3x3 box as up-to-three contiguous row-runs (sequential;
    // the interleaved variant measured slower).
    {
        int ilo = max(cx - 1, 0), ihi = min(cx + 1, G - 1);
        int jlo = max(cy - 1, 0), jhi = min(cy + 1, G - 1);
        for (int j = jlo; j <= jhi; j++)
            scan_run(s_pts, s_cs[j * G + ilo], s_cs[j * G + ihi + 1], q, best);
    }

    // Ring expansion (rare tail; edge-aware lb kills outliers at r=1).
    int r = 1;
    while (true) {
        float lb = box_lb(q.x, q.y, cx, cy, r);
        if (best <= lb * lb) break;       // inf^2 covers clamped/full coverage
        r++;
        int rlo = max(cx - r, 0), rhi = min(cx + r, G - 1);
        int jt = cy - r, jb = cy + r;
        if (jt >= 0)
            scan_run(s_pts, s_cs[jt * G + rlo], s_cs[jt * G + rhi + 1], q, best);
        if (jb <= G - 1)
            scan_run(s_pts, s_cs[jb * G + rlo], s_cs[jb * G + rhi + 1], q, best);
        int jlo2 = max(cy - r + 1, 0), jhi2 = min(cy + r - 1, G - 1);
        for (int j = jlo2; j <= jhi2; j++) {
            if (cx - r >= 0) {
                int c = j * G + (cx - r);
                scan_run(s_pts, s_cs[c], s_cs[c + 1], q, best);
            }
            if (cx + r <= G - 1) {
                int c = j * G + (cx + r);
                scan_run(s_pts, s_cs[c], s_cs[c + 1], q, best);
            }
        }
    }

    float d = sqrtf(fmaxf(best, EPS));

    // Block reduce (all threads in block share (dir, n)).
#pragma unroll
    for (int o = 16; o > 0; o >>= 1) d += __shfl_down_sync(0xffffffffu, d, o);
    if (lane == 0) s_red[w] = d;
    __syncthreads();
    if (t == 0) {
        float a = 0.0f;
#pragma unroll
        for (int ww = 0; ww < TPB / 32; ww++) a += s_red[ww];
        atomicAdd(out, a * g_mask[n] * OUT_WT);
    }
}

extern "C" void kernel_launch(void* const* d_in, const int* in_sizes, int n_in,
                              void* d_out, int out_size) {
    const float* s1 = (const float*)d_in[0];  // point_set_1: [16,4096,2] f32
    const float* s2 = (const float*)d_in[1];  // point_set_2: [16,4096,2] f32
    float* out = (float*)d_out;

    build_kernel<<<2 * N_BATCH, TPB_B>>>(s1, s2, out);
    query_kernel<<<2 * N_BATCH * (P / TPB), TPB>>>(out);
}

// round 11
// speedup vs baseline: 1.5000x; 1.4732x over previous
#include <cuda_runtime.h>
#include <stdint.h>
#include <float.h>

// ChamferLoss2D: N=16, P=4096, D=2.
// cost_n = 0.5*(mean_i min_j C + mean_j min_i C), C = sqrt(clip(|x-y|^2, EPS))
// out = mean_n cost_n * (sum(set2_n) >= 0)
//
// Grid NN, exact, SMEM-resident (points 32KB + u16 cell table 12.8KB per
// block). Dense queries: single 3x3 row-run scan + lower-bound stop. Sparse
// tail: GEOMETRIC box growth (r doubles) scanning whole rows as contiguous
// runs -- O(rows) independent bound loads instead of O(cells) serial ring
// walk. Edge-aware lower bound (clamped sides => inf) + full-coverage
// fallback => exact for ANY input.

#define N_BATCH 16
#define P 4096

#define G 80
#define CELLS (G * G)            // 6400
#define CS_PAD (CELLS + 2)

#define DOM_LO (-5.2f)
#define DOM_W  (10.4f)
#define CELL_W (DOM_W / (float)G)
#define INV_W  ((float)G / DOM_W)

#define EPS 1e-12f
#define OUT_WT (0.5f / (float)P / (float)N_BATCH)

__device__ float2   g_pts[2][N_BATCH][P];           // cell-sorted points
__device__ uint16_t g_cellstart[2][N_BATCH][CS_PAD];
__device__ float    g_mask[N_BATCH];

__device__ __forceinline__ int cell_coord(float v) {
    int c = (int)((v - DOM_LO) * INV_W);
    return min(max(c, 0), G - 1);
}

// ---- build: one block of 512 per (set, batch) -------------------------------
#define TPB_B 512
#define PPT_B (P / TPB_B)        // 8
#define CELLS_PADB 6656          // 512 * 13
#define CPT_B 13

__global__ void __launch_bounds__(TPB_B) build_kernel(
    const float* __restrict__ s1, const float* __restrict__ s2,
    float* __restrict__ out) {
    const int set = blockIdx.x >> 4;
    const int n   = blockIdx.x & 15;
    const float2* __restrict__ src =
        (const float2*)((set ? s2 : s1) + (size_t)n * P * 2);

    __shared__ uint32_t s_cnt[CELLS_PADB];
    __shared__ uint32_t s_wsum[TPB_B / 32];
    __shared__ float    s_red[TPB_B / 32];

    const int t = threadIdx.x;
    const int lane = t & 31, w = t >> 5;

#pragma unroll
    for (int k = 0; k < CPT_B; k++) s_cnt[k * TPB_B + t] = 0;
    __syncthreads();

    float2 pt[PPT_B];
    int    cid[PPT_B];
    float  msum = 0.0f;
#pragma unroll
    for (int k = 0; k < PPT_B; k++) {
        float2 p = src[k * TPB_B + t];
        pt[k] = p;
        cid[k] = cell_coord(p.y) * G + cell_coord(p.x);
        atomicAdd(&s_cnt[cid[k]], 1u);
        msum += p.x + p.y;
    }
    __syncthreads();

    uint32_t tot = 0;
#pragma unroll
    for (int c = 0; c < CPT_B; c++) tot += s_cnt[t * CPT_B + c];
    uint32_t inc = tot;
#pragma unroll
    for (int o = 1; o < 32; o <<= 1) {
        uint32_t v = __shfl_up_sync(0xffffffffu, inc, o);
        if (lane >= o) inc += v;
    }
    if (lane == 31) s_wsum[w] = inc;
    uint32_t excl = inc - tot;
    __syncthreads();
    uint32_t wbase = 0;
#pragma unroll
    for (int ww = 0; ww < TPB_B / 32; ww++) {
        uint32_t v = s_wsum[ww];
        if (ww < w) wbase += v;
    }
    uint32_t run = wbase + excl;
#pragma unroll
    for (int c = 0; c < CPT_B; c++) {
        uint32_t v = s_cnt[t * CPT_B + c];
        s_cnt[t * CPT_B + c] = run;
        run += v;
    }
    __syncthreads();

    uint16_t* __restrict__ gs = g_cellstart[set][n];
#pragma unroll
    for (int k = 0; k < CPT_B; k++) {
        int i = k * TPB_B + t;
        if (i < CS_PAD) gs[i] = (uint16_t)s_cnt[i];
    }
    __syncthreads();

    float2* __restrict__ gp = g_pts[set][n];
#pragma unroll
    for (int k = 0; k < PPT_B; k++) {
        uint32_t pos = atomicAdd(&s_cnt[cid[k]], 1u);
        gp[pos] = pt[k];
    }

#pragma unroll
    for (int o = 16; o > 0; o >>= 1) msum += __shfl_down_sync(0xffffffffu, msum, o);
    if (lane == 0) s_red[w] = msum;
    __syncthreads();
    if (t == 0) {
        float a = 0.0f;
#pragma unroll
        for (int ww = 0; ww < TPB_B / 32; ww++) a += s_red[ww];
        if (set == 1) g_mask[n] = (a >= 0.0f) ? 1.0f : 0.0f;
        if (set == 0 && n == 0) out[0] = 0.0f;
    }
}

// ---- query ------------------------------------------------------------------
#define TPB 256

__device__ __forceinline__ float sqd(float2 q, float2 p) {
    float dx = q.x - p.x;
    float dy = q.y - p.y;
    return fmaf(dx, dx, dy * dy);
}

__device__ __forceinline__ void scan_run(
    const float2* pts, int s, int e, float2 q, float& best) {
    for (int idx = s; idx < e; idx++)
        best = fminf(best, sqd(q, pts[idx]));
}

// Lower bound to unscanned region outside box radius r; clamped sides => inf.
__device__ __forceinline__ float box_lb(float qx, float qy, int cx, int cy, int r) {
    float l  = (cx - r <= 0)     ? FLT_MAX : qx - (DOM_LO + (float)(cx - r) * CELL_W);
    float rt = (cx + r >= G - 1) ? FLT_MAX : (DOM_LO + (float)(cx + r + 1) * CELL_W) - qx;
    float b  = (cy - r <= 0)     ? FLT_MAX : qy - (DOM_LO + (float)(cy - r) * CELL_W);
    float tp = (cy + r >= G - 1) ? FLT_MAX : (DOM_LO + (float)(cy + r + 1) * CELL_W) - qy;
    return fminf(fminf(l, rt), fminf(b, tp));
}

__global__ void __launch_bounds__(TPB) query_kernel(float* __restrict__ out) {
    // blockIdx: [dir(2)][n(16)][chunk(16)]
    const int chunk = blockIdx.x & 15;
    const int n     = (blockIdx.x >> 4) & 15;
    const int dir   = blockIdx.x >> 8;
    const int dst   = 1 - dir;
    const int t     = threadIdx.x;
    const int lane  = t & 31;
    const int w     = t >> 5;

    __shared__ __align__(16) float2   s_pts[P];       // 32 KB
    __shared__ __align__(4)  uint16_t s_cs[CS_PAD];   // 12.8 KB
    __shared__ float s_red[TPB / 32];

    // Copy destination structure into smem (L2 hits, coalesced).
    {
        const float4* gp4 = (const float4*)g_pts[dst][n];
        float4* sp4 = (float4*)s_pts;
#pragma unroll
        for (int k = 0; k < (P / 2) / TPB; k++)
            sp4[k * TPB + t] = gp4[k * TPB + t];
        const uint32_t* gc = (const uint32_t*)g_cellstart[dst][n];
        uint32_t* sc = (uint32_t*)s_cs;
        for (int i = t; i < CS_PAD / 2; i += TPB)
            sc[i] = gc[i];
    }

    // Warp-shuffled query assignment: every block gets a uniform mix of
    // dense and sparse sorted regions; queries stay warp-contiguous.
    const int qidx = (w * 16 + chunk) * 32 + lane;
    const float2 q = g_pts[dir][n][qidx];
    const int cx = cell_coord(q.x);
    const int cy = cell_coord(q.y);

    __syncthreads();

    float best = FLT_MAX;

    // Fast path: 3x3 box as up-to-three contiguous row-runs.
    {
        int ilo = max(cx - 1, 0), ihi = min(cx + 1, G - 1);
        int jlo = max(cy - 1, 0), jhi = min(cy + 1, G - 1);
        for (int j = jlo; j <= jhi; j++)
            scan_run(s_pts, s_cs[j * G + ilo], s_cs[j * G + ihi + 1], q, best);
    }

    // Sparse tail: geometric box growth, whole-row runs (rescans are
    // idempotent and cheap in sparse regions; dense queries never get here).
    int r = 1;
    while (true) {
        float lb = box_lb(q.x, q.y, cx, cy, r);
        if (best <= lb * lb) break;       // inf^2 covers clamped/full coverage
        r = min(2 * r, G);
        int ilo = max(cx - r, 0), ihi = min(cx + r, G - 1);
        int jlo = max(cy - r, 0), jhi = min(cy + r, G - 1);
        for (int j = jlo; j <= jhi; j++)
            scan_run(s_pts, s_cs[j * G + ilo], s_cs[j * G + ihi + 1], q, best);
    }

    float d = sqrtf(fmaxf(best, EPS));

    // Block reduce (all threads in block share (dir, n)).
#pragma unroll
    for (int o = 16; o > 0; o >>= 1) d += __shfl_down_sync(0xffffffffu, d, o);
    if (lane == 0) s_red[w] = d;
    __syncthreads();
    if (t == 0) {
        float a = 0.0f;
#pragma unroll
        for (int ww = 0; ww < TPB / 32; ww++) a += s_red[ww];
        atomicAdd(out, a * g_mask[n] * OUT_WT);
    }
}

extern "C" void kernel_launch(void* const* d_in, const int* in_sizes, int n_in,
                              void* d_out, int out_size) {
    const float* s1 = (const float*)d_in[0];  // point_set_1: [16,4096,2] f32
    const float* s2 = (const float*)d_in[1];  // point_set_2: [16,4096,2] f32
    float* out = (float*)d_out;

    build_kernel<<<2 * N_BATCH, TPB_B>>>(s1, s2, out);
    query_kernel<<<2 * N_BATCH * (P / TPB), TPB>>>(out);
}